// round 3
// baseline (speedup 1.0000x reference)
#include <cuda_runtime.h>

// ---------------------------------------------------------------------------
// HiggsAudioModel merge — R3: setup (1 CTA) -> fused meta+pos (8 CTAs) ->
// streaming bulk copy. B=8, S=2048, D=2048, M=4088.
// Output = concat(embedding (B,M,D), attention, labels, position_ids,
//                 input_ids, in_fill, in_discrete, out_fill) all f32.
// ---------------------------------------------------------------------------

#define TOK_IN   128011
#define TOK_OUT  128012
#define TOK_PAD  128001
#define LBL_IGN  (-100)

static constexpr int B_ = 8, S_ = 2048, D_ = 2048, M_ = 4088, MAXP = 64;
static constexpr int BS_ = B_ * S_;
static constexpr int BM_ = B_ * M_;

// per merged position: text row (0..BS_-1), BS_+audio row, or -1 (pad)
__device__ int g_src[BM_];

__device__ __forceinline__ int wscan_incl(int v) {
    int lane = threadIdx.x & 31;
    #pragma unroll
    for (int o = 1; o < 32; o <<= 1) {
        int n = __shfl_up_sync(0xffffffffu, v, o);
        if (lane >= o) v += n;
    }
    return v;
}

// ---- A: full setup in one CTA (1024 threads, 16 ids per thread) ------------
__global__ void __launch_bounds__(1024) k_setup(
        const int* __restrict__ ids_g,
        const int* __restrict__ in_starts, const int* __restrict__ out_starts,
        int n_in, int n_out, int tot_in, int tot_out) {
    __shared__ int s_in_len[MAXP], s_out_len[MAXP];
    __shared__ int s_in_st[MAXP], s_out_st[MAXP];
    __shared__ int s_w_in[32], s_w_out[32], s_w_tpn[32];
    __shared__ int s_seg_b[2 * MAXP], s_seg_end[2 * MAXP];  // [0,MAXP)=in

    int tid = threadIdx.x;
    int lane = tid & 31, warp = tid >> 5;
    int b = tid >> 7;                       // 128 threads per row

    if (tid < n_in) {
        int st = in_starts[tid];
        s_in_st[tid] = st;
        s_in_len[tid] = ((tid + 1 < n_in) ? in_starts[tid + 1] : tot_in) - st;
    }
    if (tid < n_out) {
        int st = out_starts[tid];
        s_out_st[tid] = st;
        s_out_len[tid] = ((tid + 1 < n_out) ? out_starts[tid + 1] : tot_out) - st;
    }
    // init g_src = -1 (vectorized; BM_ divisible by 4)
    {
        int4* p = (int4*)g_src;
        int4 mm = make_int4(-1, -1, -1, -1);
        for (int i = tid; i < BM_ / 4; i += 1024) p[i] = mm;
    }
    // load this thread's 16 ids
    int idl[16];
    {
        const int4* p = (const int4*)(ids_g + tid * 16);
        #pragma unroll
        for (int j = 0; j < 4; j++) {
            int4 v = p[j];
            idl[4*j+0] = v.x; idl[4*j+1] = v.y; idl[4*j+2] = v.z; idl[4*j+3] = v.w;
        }
    }
    int cin = 0, cout = 0;
    #pragma unroll
    for (int j = 0; j < 16; j++) { cin += (idl[j] == TOK_IN); cout += (idl[j] == TOK_OUT); }

    // global (cross-row, row-major) exclusive scan of placeholder counts
    int sin = wscan_incl(cin), sout = wscan_incl(cout);
    if (lane == 31) { s_w_in[warp] = sin; s_w_out[warp] = sout; }
    __syncthreads();
    if (warp == 0) {
        int vi = s_w_in[lane], vo = s_w_out[lane];
        int si = wscan_incl(vi), so = wscan_incl(vo);
        s_w_in[lane] = si - vi;             // exclusive warp offsets
        s_w_out[lane] = so - vo;
    }
    __syncthreads();
    int rank_in  = s_w_in[warp]  + sin  - cin;   // global ordinal of my first IN
    int rank_out = s_w_out[warp] + sout - cout;

    // tokens-per-slot chunk sum (placeholder -> code length)
    int tsum = 0;
    {
        int ri = rank_in, ro = rank_out;
        #pragma unroll
        for (int j = 0; j < 16; j++) {
            int id = idl[j];
            int v = 1;
            if (id == TOK_IN)       v = s_in_len[ri++];
            else if (id == TOK_OUT) v = s_out_len[ro++];
            tsum += v;
        }
    }
    // segmented (per-row) scan: 4 warps per row
    int stpn = wscan_incl(tsum);
    if (lane == 31) s_w_tpn[warp] = stpn;
    __syncthreads();
    int wir = warp & 3, wbase = warp & ~3;
    int excl = 0, rowtot = 0;
    #pragma unroll
    for (int w = 0; w < 4; w++) {
        int v = s_w_tpn[wbase + w];
        if (w < wir) excl += v;
        rowtot += v;
    }
    int shift = M_ - rowtot;                // left-pad shift
    int cum = excl + stpn - tsum;           // exclusive prefix within row
    {
        int ri = rank_in, ro = rank_out;
        #pragma unroll
        for (int j = 0; j < 16; j++) {
            int id = idl[j];
            int v = 1;
            if (id == TOK_IN)       v = s_in_len[ri];
            else if (id == TOK_OUT) v = s_out_len[ro];
            cum += v;
            int np = cum - 1 + shift;       // merged column of this slot
            if (id == TOK_IN)       { s_seg_b[ri] = b;        s_seg_end[ri] = np;        ri++; }
            else if (id == TOK_OUT) { s_seg_b[MAXP+ro] = b;   s_seg_end[MAXP+ro] = np;   ro++; }
            else                    g_src[b * M_ + np] = tid * 16 + j;   // text
        }
    }
    __syncthreads();
    // map each audio code row -> merged position
    int total = tot_in + tot_out;
    for (int i = tid; i < total; i += 1024) {
        bool isin = i < tot_in;
        int r = isin ? i : i - tot_in;
        const int* st = isin ? s_in_st : s_out_st;
        int n = isin ? n_in : n_out;
        int lo = 0, hi = n;                 // searchsorted(right)-1
        while (lo < hi) { int mid = (lo + hi) >> 1; if (st[mid] <= r) lo = mid + 1; else hi = mid; }
        int p = lo - 1;
        int len = isin ? s_in_len[p]  : s_out_len[p];
        int end = isin ? s_seg_end[p] : s_seg_end[MAXP + p];
        int bb  = isin ? s_seg_b[p]   : s_seg_b[MAXP + p];
        int c = end - len + 1 + (r - st[p]);
        g_src[bb * M_ + c] = BS_ + i;
    }
}

// ---- B: ALL scalar metadata incl. position_ids, one CTA per merged row -----
// attn derived analytically from g_src (never reads d_out back).
__global__ void __launch_bounds__(1024) k_metapos(
        const int* __restrict__ ids, const int* __restrict__ labels,
        const int* __restrict__ amask, int tot_in,
        float* __restrict__ out) {
    int bb = blockIdx.x, t = threadIdx.x;   // 1024 threads, 4 elems each
    int lane = t & 31, warp = t >> 5;       // 32 warps
    __shared__ int s_w[32];
    const size_t BM = (size_t)BM_;
    float* meta = out + (size_t)BM_ * D_;

    int base = bb * M_ + t * 4;             // global merged index of elem 0
    int a[4];                                // attention bits
    float lbl[4], iid[4], fin[4], find[4], fout[4];
    #pragma unroll
    for (int j = 0; j < 4; j++) {
        int col = t * 4 + j;
        int av = 0;
        float l = (float)LBL_IGN, id = (float)TOK_PAD;
        float fi = 0.f, fd = 0.f, fo = 0.f;
        if (col < M_) {
            int si = g_src[base + j];
            if (si >= 0) {
                if (si < BS_) {
                    av = __ldg(amask + si);
                    l  = (float)__ldg(labels + si);
                    id = (float)__ldg(ids + si);
                } else {
                    av = 1;
                    int r = si - BS_;
                    if (r < tot_in) { id = (float)TOK_IN;  fi = 1.f; fd = 1.f; }
                    else            { id = (float)TOK_OUT; fo = 1.f; }
                }
            }
        }
        a[j] = av; lbl[j] = l; iid[j] = id; fin[j] = fi; find[j] = fd; fout[j] = fo;
    }
    int s = a[0] + a[1] + a[2] + a[3];
    int sc = wscan_incl(s);
    if (lane == 31) s_w[warp] = sc;
    __syncthreads();
    int excl = 0;
    if (warp > 0) {
        // warp-parallel reduction of preceding warp sums via warp 0 shuffle:
        // cheap serial is fine (32 adds)
        #pragma unroll
        for (int w = 0; w < 32; w++) if (w < warp) excl += s_w[w];
    }
    int cum = excl + sc - s;
    #pragma unroll
    for (int j = 0; j < 4; j++) {
        int col = t * 4 + j;
        if (col >= M_) break;
        cum += a[j];
        size_t o = (size_t)bb * M_ + col;
        meta[o]          = (float)a[j];
        meta[BM + o]     = lbl[j];
        meta[2 * BM + o] = (float)((a[j] == 0) ? 1 : (cum - 1));  // position_ids
        meta[3 * BM + o] = iid[j];
        meta[4 * BM + o] = fin[j];
        meta[5 * BM + o] = find[j];
        meta[6 * BM + o] = fout[j];
    }
}

// ---- C: heavy row gather (one CTA per merged row, streaming hints) ---------
__global__ void __launch_bounds__(256) k_copy(const float4* __restrict__ in_e,
                                              const float4* __restrict__ out_e,
                                              const float4* __restrict__ txt_e,
                                              int tot_in,
                                              float4* __restrict__ dst_all) {
    int row = blockIdx.x;
    int si = g_src[row];
    float4* dst = dst_all + (size_t)row * (D_ / 4);
    int t = threadIdx.x;
    if (si < 0) {
        float4 z = make_float4(0.f, 0.f, 0.f, 0.f);
        __stcs(dst + t, z);
        __stcs(dst + t + 256, z);
        return;
    }
    const float4* src;
    if (si < BS_) src = txt_e + (size_t)si * (D_ / 4);
    else {
        int r = si - BS_;
        src = (r < tot_in) ? in_e + (size_t)r * (D_ / 4)
                           : out_e + (size_t)(r - tot_in) * (D_ / 4);
    }
    float4 v0 = __ldcs(src + t);
    float4 v1 = __ldcs(src + t + 256);
    __stcs(dst + t, v0);
    __stcs(dst + t + 256, v1);
}

// ------------------------------- launcher ----------------------------------
extern "C" void kernel_launch(void* const* d_in, const int* in_sizes, int n_in_args,
                              void* d_out, int out_size) {
    const float* a_in_e  = (const float*)d_in[0];
    const float* a_out_e = (const float*)d_in[1];
    const float* txt_e   = (const float*)d_in[2];
    const int* in_starts  = (const int*)d_in[3];
    const int* out_starts = (const int*)d_in[4];
    const int* ids    = (const int*)d_in[5];
    const int* amask  = (const int*)d_in[6];
    const int* labels = (const int*)d_in[7];

    const int tot_in  = in_sizes[0] / D_;
    const int tot_out = in_sizes[1] / D_;
    const int n_in  = in_sizes[3];
    const int n_out = in_sizes[4];

    float* out = (float*)d_out;

    k_setup<<<1, 1024>>>(ids, in_starts, out_starts, n_in, n_out, tot_in, tot_out);
    k_metapos<<<B_, 1024>>>(ids, labels, amask, tot_in, out);
    k_copy<<<BM_, 256>>>((const float4*)a_in_e, (const float4*)a_out_e,
                         (const float4*)txt_e, tot_in, (float4*)out);
}

// round 4
// speedup vs baseline: 1.1543x; 1.1543x over previous
#include <cuda_runtime.h>

// ---------------------------------------------------------------------------
// HiggsAudioModel merge — R4: one fused per-row prologue kernel (grid=8,
// builds src map in SMEM + writes all metadata) -> streaming bulk copy.
//   B=8, S=2048, D=2048, M=4088.
// Output = concat(embedding (B,M,D), attention, labels, position_ids,
//                 input_ids, in_fill, in_discrete, out_fill) all f32.
// ---------------------------------------------------------------------------

#define TOK_IN   128011
#define TOK_OUT  128012
#define TOK_PAD  128001
#define LBL_IGN  (-100)

static constexpr int B_ = 8, S_ = 2048, D_ = 2048, M_ = 4088, MAXP = 64;
static constexpr int BS_ = B_ * S_;
static constexpr int BM_ = B_ * M_;

// per merged position: text row (0..BS_-1), BS_+audio row, or -1 (pad)
__device__ int g_src[BM_];

__device__ __forceinline__ int wscan_incl(int v) {
    int lane = threadIdx.x & 31;
    #pragma unroll
    for (int o = 1; o < 32; o <<= 1) {
        int n = __shfl_up_sync(0xffffffffu, v, o);
        if (lane >= o) v += n;
    }
    return v;
}

// ---- A: fused per-row prologue: mapping + g_src + ALL metadata -------------
__global__ void __launch_bounds__(1024) k_map(
        const int* __restrict__ ids_g,
        const int* __restrict__ in_starts, const int* __restrict__ out_starts,
        const int* __restrict__ labels, const int* __restrict__ amask,
        int n_in, int n_out, int tot_in, int tot_out,
        float* __restrict__ out) {
    __shared__ __align__(16) int s_src[M_];
    __shared__ int s_w0[32], s_w1[32];      // scan staging
    __shared__ int s_segi_end[MAXP], s_sego_end[MAXP];
    __shared__ int s_base[2], s_tot[3];

    const int b = blockIdx.x, tid = threadIdx.x;
    const int lane = tid & 31, warp = tid >> 5;

    // init shared src row to -1
    #pragma unroll
    for (int i = tid; i < M_; i += 1024) s_src[i] = -1;

    // ---- 1) count placeholders in preceding rows (global row-major order) --
    int pin = 0, pout = 0;
    {
        const int4* p = (const int4*)ids_g;
        const int n4 = b * S_ / 4;
        for (int i = tid; i < n4; i += 1024) {
            int4 v = p[i];
            pin  += (v.x == TOK_IN) + (v.y == TOK_IN) + (v.z == TOK_IN) + (v.w == TOK_IN);
            pout += (v.x == TOK_OUT) + (v.y == TOK_OUT) + (v.z == TOK_OUT) + (v.w == TOK_OUT);
        }
        #pragma unroll
        for (int o = 16; o > 0; o >>= 1) {
            pin  += __shfl_down_sync(0xffffffffu, pin, o);
            pout += __shfl_down_sync(0xffffffffu, pout, o);
        }
        if (lane == 0) { s_w0[warp] = pin; s_w1[warp] = pout; }
        __syncthreads();
        if (tid == 0) {
            int a = 0, c = 0;
            #pragma unroll
            for (int w = 0; w < 32; w++) { a += s_w0[w]; c += s_w1[w]; }
            s_base[0] = a; s_base[1] = c;
        }
        __syncthreads();
    }
    const int base_in = s_base[0], base_out = s_base[1];

    // ---- 2) own row: scan placeholder ordinals + tokens-per-slot -----------
    int id0, id1;
    {
        int2 v = ((const int2*)(ids_g + b * S_))[tid];
        id0 = v.x; id1 = v.y;
    }
    int cin  = (id0 == TOK_IN)  + (id1 == TOK_IN);
    int cout = (id0 == TOK_OUT) + (id1 == TOK_OUT);
    __syncthreads();   // reuse of s_w0/s_w1

    // packed scan of (cin, cout): each fits in 16 bits
    int packed = cin | (cout << 16);
    int psc = wscan_incl(packed);
    if (lane == 31) s_w0[warp] = psc;
    __syncthreads();
    int pexcl = 0;
    #pragma unroll
    for (int w = 0; w < 32; w++) if (w < warp) pexcl += s_w0[w];
    int scin  = pexcl + psc;                // inclusive row prefix, packed
    int ri0 = base_in  + (scin & 0xffff) - cin;      // global ordinal of my first IN
    int ro0 = base_out + (scin >> 16) - cout;
    if (tid == 1023) {
        s_tot[0] = scin & 0xffff;           // row in-count
        s_tot[1] = scin >> 16;              // row out-count
    }

    // tokens-per-slot (placeholder -> its code length, else 1)
    int v0 = 1, v1 = 1;
    {
        int ri = ri0, ro = ro0;
        if (id0 == TOK_IN)       { v0 = ((ri+1 < n_in)  ? __ldg(in_starts+ri+1)  : tot_in)  - __ldg(in_starts+ri);  ri++; }
        else if (id0 == TOK_OUT) { v0 = ((ro+1 < n_out) ? __ldg(out_starts+ro+1) : tot_out) - __ldg(out_starts+ro); ro++; }
        if (id1 == TOK_IN)       { v1 = ((ri+1 < n_in)  ? __ldg(in_starts+ri+1)  : tot_in)  - __ldg(in_starts+ri); }
        else if (id1 == TOK_OUT) { v1 = ((ro+1 < n_out) ? __ldg(out_starts+ro+1) : tot_out) - __ldg(out_starts+ro); }
    }
    int tsum = v0 + v1;
    __syncthreads();
    int tsc = wscan_incl(tsum);
    if (lane == 31) s_w1[warp] = tsc;
    __syncthreads();
    int texcl = 0, rowtot = 0;
    #pragma unroll
    for (int w = 0; w < 32; w++) {
        int x = s_w1[w];
        if (w < warp) texcl += x;
        rowtot += x;
    }
    const int shift = M_ - rowtot;          // left-pad shift
    int cum = texcl + tsc - tsum;           // exclusive prefix within row

    // scatter text positions / record placeholder segment ends (in SMEM)
    {
        int ri = ri0 - base_in, ro = ro0 - base_out;   // local ordinals
        cum += v0;
        int np = cum - 1 + shift;
        if (id0 == TOK_IN)       s_segi_end[ri++] = np;
        else if (id0 == TOK_OUT) s_sego_end[ro++] = np;
        else                     s_src[np] = b * S_ + tid * 2;
        cum += v1;
        np = cum - 1 + shift;
        if (id1 == TOK_IN)       s_segi_end[ri] = np;
        else if (id1 == TOK_OUT) s_sego_end[ro] = np;
        else                     s_src[np] = b * S_ + tid * 2 + 1;
    }
    __syncthreads();

    // ---- 3) audio code rows of this row's placeholders (coalesced) ---------
    const int cin_row = s_tot[0], cout_row = s_tot[1];
    for (int lp = 0; lp < cin_row; lp++) {
        int g = base_in + lp;
        int st = __ldg(in_starts + g);
        int len = ((g + 1 < n_in) ? __ldg(in_starts + g + 1) : tot_in) - st;
        int colstart = s_segi_end[lp] - len + 1;
        for (int k = tid; k < len; k += 1024)
            s_src[colstart + k] = BS_ + st + k;
    }
    for (int lp = 0; lp < cout_row; lp++) {
        int g = base_out + lp;
        int st = __ldg(out_starts + g);
        int len = ((g + 1 < n_out) ? __ldg(out_starts + g + 1) : tot_out) - st;
        int colstart = s_sego_end[lp] - len + 1;
        for (int k = tid; k < len; k += 1024)
            s_src[colstart + k] = BS_ + tot_in + st + k;
    }
    __syncthreads();

    // ---- 4) dump g_src row + compute all metadata from SMEM ----------------
    {
        int4* dst = (int4*)(g_src + b * M_);
        const int4* srcp = (const int4*)s_src;
        #pragma unroll
        for (int i = tid; i < M_ / 4; i += 1024) dst[i] = srcp[i];
    }

    const size_t BM = (size_t)BM_;
    float* meta = out + (size_t)BM_ * D_;
    int a[4];
    float lblv[4], iidv[4], fin[4], find[4], fout[4];
    #pragma unroll
    for (int j = 0; j < 4; j++) {
        int col = tid * 4 + j;
        int av = 0;
        float l = (float)LBL_IGN, idv = (float)TOK_PAD;
        float fi = 0.f, fd = 0.f, fo = 0.f;
        if (col < M_) {
            int si = s_src[col];
            if (si >= 0) {
                if (si < BS_) {
                    av  = __ldg(amask + si);
                    l   = (float)__ldg(labels + si);
                    idv = (float)__ldg(ids_g + si);
                } else {
                    av = 1;
                    int r = si - BS_;
                    if (r < tot_in) { idv = (float)TOK_IN;  fi = 1.f; fd = 1.f; }
                    else            { idv = (float)TOK_OUT; fo = 1.f; }
                }
            }
        }
        a[j] = av; lblv[j] = l; iidv[j] = idv; fin[j] = fi; find[j] = fd; fout[j] = fo;
    }
    int s = a[0] + a[1] + a[2] + a[3];
    __syncthreads();   // s_w0 reuse
    int sc = wscan_incl(s);
    if (lane == 31) s_w0[warp] = sc;
    __syncthreads();
    int excl = 0;
    #pragma unroll
    for (int w = 0; w < 32; w++) if (w < warp) excl += s_w0[w];
    int pc = excl + sc - s;
    #pragma unroll
    for (int j = 0; j < 4; j++) {
        int col = tid * 4 + j;
        if (col >= M_) break;
        pc += a[j];
        size_t o = (size_t)b * M_ + col;
        meta[o]          = (float)a[j];
        meta[BM + o]     = lblv[j];
        meta[2 * BM + o] = (float)((a[j] == 0) ? 1 : (pc - 1));   // position_ids
        meta[3 * BM + o] = iidv[j];
        meta[4 * BM + o] = fin[j];
        meta[5 * BM + o] = find[j];
        meta[6 * BM + o] = fout[j];
    }
}

// ---- B: heavy row gather (one CTA per merged row, streaming hints) ---------
__global__ void __launch_bounds__(256) k_copy(const float4* __restrict__ in_e,
                                              const float4* __restrict__ out_e,
                                              const float4* __restrict__ txt_e,
                                              int tot_in,
                                              float4* __restrict__ dst_all) {
    int row = blockIdx.x;
    int si = g_src[row];
    float4* dst = dst_all + (size_t)row * (D_ / 4);
    int t = threadIdx.x;
    if (si < 0) {
        float4 z = make_float4(0.f, 0.f, 0.f, 0.f);
        __stcs(dst + t, z);
        __stcs(dst + t + 256, z);
        return;
    }
    const float4* src;
    if (si < BS_) src = txt_e + (size_t)si * (D_ / 4);
    else {
        int r = si - BS_;
        src = (r < tot_in) ? in_e + (size_t)r * (D_ / 4)
                           : out_e + (size_t)(r - tot_in) * (D_ / 4);
    }
    float4 a0 = __ldcs(src + t);
    float4 a1 = __ldcs(src + t + 256);
    __stcs(dst + t, a0);
    __stcs(dst + t + 256, a1);
}

// ------------------------------- launcher ----------------------------------
extern "C" void kernel_launch(void* const* d_in, const int* in_sizes, int n_in_args,
                              void* d_out, int out_size) {
    const float* a_in_e  = (const float*)d_in[0];
    const float* a_out_e = (const float*)d_in[1];
    const float* txt_e   = (const float*)d_in[2];
    const int* in_starts  = (const int*)d_in[3];
    const int* out_starts = (const int*)d_in[4];
    const int* ids    = (const int*)d_in[5];
    const int* amask  = (const int*)d_in[6];
    const int* labels = (const int*)d_in[7];

    const int tot_in  = in_sizes[0] / D_;
    const int tot_out = in_sizes[1] / D_;
    const int n_in  = in_sizes[3];
    const int n_out = in_sizes[4];

    float* out = (float*)d_out;

    k_map<<<B_, 1024>>>(ids, in_starts, out_starts, labels, amask,
                        n_in, n_out, tot_in, tot_out, out);
    k_copy<<<BM_, 256>>>((const float4*)a_in_e, (const float4*)a_out_e,
                         (const float4*)txt_e, tot_in, (float4*)out);
}